// round 16
// baseline (speedup 1.0000x reference)
#include <cuda_runtime.h>
#include <cstdint>

#define T_STEPS 64
#define BATCH   128
#define HID     1024
#define INP     1024
#define KTOT    1025
#define GCOLS   2048
#define SRC_PITCH 1032          // u16 pitch
#define ACC_LIM 256.0f

// smem (step kernel): three 48KB stages + 16KB gsm + mbarriers
#define STAGE_STRIDE 49152
#define NSTAGE 3
#define SX_OFF 0
#define SH_OFF 8192
#define SW_OFF 16384
#define GSM_OFF (NSTAGE * STAGE_STRIDE)
#define MBAR_OFF (GSM_OFF + 16384)
#define SMEM_TOTAL (MBAR_OFF + 128)

#define W_CHUNK_BYTES 32768
#define A_CHUNK_BYTES 8192
#define FILL_BYTES (W_CHUNK_BYTES + 2 * A_CHUNK_BYTES)   // 49152
#define HIMG_PAR_STRIDE (4 * 4 * A_CHUNK_BYTES)

// ---- static device state ----
__device__ __align__(16) uint16_t g_src[2][GCOLS * SRC_PITCH];
__device__ float    g_C[2][T_STEPS * GCOLS];
__device__ int      g_rngW[256];
__device__ int      g_rngWI[256];
__device__ int      g_rngM[16];
// pre-swizzled stage images
__device__ __align__(16) int8_t   g_w8[(size_t)T_STEPS * 32 * 4 * W_CHUNK_BYTES];   // [t][jx][chunk][32KB]
__device__ __align__(16) uint8_t  g_ximg[(size_t)T_STEPS * 4 * 4 * A_CHUNK_BYTES];  // [t][by][chunk][8KB]
__device__ __align__(16) uint8_t  g_himg[2 * HIMG_PAR_STRIDE];                       // [par][by][chunk][8KB]
__device__ int      g_hbar[16];   // per (by, j-chunk) producer barrier

// ---- warp-cooperative numpy RandomState(seed).permutation(n), bit-exact ----
__device__ void warp_fill_perm(int lane, uint32_t seed, int n, int* out,
                               uint32_t* mt, uint32_t* y, uint32_t* tp,
                               int* arr, volatile int* pstate) {
    if (lane == 0) {
        uint32_t s = seed;
        for (int i = 0; i < 624; i++) { mt[i] = s; s = 1812433253u * (s ^ (s >> 30)) + (uint32_t)i + 1u; }
        *pstate = n - 1;
    }
    for (int i = lane; i < n; i += 32) arr[i] = i;
    __syncwarp();
    int i_rem = n - 1;
    while (i_rem > 0) {
        for (int k = lane; k < 623; k += 32)
            y[k] = (mt[k] & 0x80000000u) | (mt[k + 1] & 0x7fffffffu);
        __syncwarp();
        for (int k = lane; k < 227; k += 32) {
            uint32_t yy = y[k];
            mt[k] = mt[k + 397] ^ (yy >> 1) ^ ((yy & 1u) ? 0x9908b0dfu : 0u);
        }
        __syncwarp();
        for (int k = 227 + lane; k < 454; k += 32) {
            uint32_t yy = y[k];
            mt[k] = mt[k - 227] ^ (yy >> 1) ^ ((yy & 1u) ? 0x9908b0dfu : 0u);
        }
        __syncwarp();
        for (int k = 454 + lane; k < 624; k += 32) {
            uint32_t yy = (k == 623) ? ((mt[623] & 0x80000000u) | (mt[0] & 0x7fffffffu)) : y[k];
            mt[k] = mt[k - 227] ^ (yy >> 1) ^ ((yy & 1u) ? 0x9908b0dfu : 0u);
        }
        __syncwarp();
        for (int k = lane; k < 624; k += 32) {
            uint32_t v = mt[k];
            v ^= v >> 11; v ^= (v << 7) & 0x9d2c5680u; v ^= (v << 15) & 0xefc60000u; v ^= v >> 18;
            tp[k] = v;
        }
        __syncwarp();
        if (lane == 0) {
            int i = *pstate;
            int pos = 0;
            while (i > 0) {
                uint32_t mask = (uint32_t)i;
                mask |= mask >> 1; mask |= mask >> 2; mask |= mask >> 4; mask |= mask >> 8; mask |= mask >> 16;
                uint32_t j = 0; int got = 0;
                while (pos < 624) {
                    j = tp[pos++] & mask;
                    if (j <= (uint32_t)i) { got = 1; break; }
                }
                if (!got) break;
                int tmp = arr[i]; arr[i] = arr[j]; arr[j] = tmp;
                i--;
            }
            *pstate = i;
        }
        __syncwarp();
        i_rem = *pstate;
        __syncwarp();
    }
    for (int k = lane; k < n; k += 32) out[k] = arr[k];
}

__device__ __forceinline__ int wval(int s, int rp, int ri) {
    return (s > rp) + (s > ri) - 1;
}

// ---- launch 1: quant | xpack(x image) | state_init | rng ----
#define SA_QUANT 16408
#define SA_XP    2048
#define SA_SI    512
__global__ __launch_bounds__(256) void setup_a_kernel(const float* __restrict__ wih, const float* __restrict__ bih,
                                                      const float* __restrict__ whh, const float* __restrict__ bhh,
                                                      const float* __restrict__ x, const float* __restrict__ hx0) {
    const int bid = blockIdx.x;
    const int tid = threadIdx.x;

    if (bid < SA_QUANT) {
        long long idx = (long long)bid * 256 + tid;
        const long long total = 2LL * GCOLS * KTOT;
        if (idx >= total) return;
        int m = (int)(idx / (GCOLS * KTOT));
        int r = (int)(idx % (GCOLS * KTOT));
        int j = r / KTOT, k = r % KTOT;
        const float* w = m ? whh : wih;
        const float* b = m ? bhh : bih;
        float v = (k < INP) ? w[(size_t)j * INP + k] : b[j];
        v = fminf(fmaxf(v, -1.0f), 1.0f);
        v = (v + 1.0f) * 0.5f * 256.0f;
        g_src[m][(size_t)j * SRC_PITCH + k] = (uint16_t)__float2int_rn(v);
        return;
    }
    if (bid < SA_QUANT + SA_XP) {
        int idx = (bid - SA_QUANT) * 256 + tid;
        int u     = idx & 511;
        int chunk = (idx >> 9) & 3;
        int by    = (idx >> 11) & 3;
        int t     = idx >> 13;
        int sub = u >> 8;
        int rem = u & 255;
        int r = rem >> 3;
        int c16 = rem & 7;
        int b = by * 32 + r;
        int k = chunk * 256 + sub * 128 + ((c16 ^ (r & 7)) << 4);
        const float* xs = x + ((size_t)t * BATCH + b) * INP + k;
        uint32_t w[4];
#pragma unroll
        for (int q = 0; q < 4; q++) {
            float4 v = *(const float4*)(xs + q * 4);
            w[q] = (uint32_t)v.x | ((uint32_t)v.y << 8) | ((uint32_t)v.z << 16) | ((uint32_t)v.w << 24);
        }
        *(uint4*)(g_ximg + (size_t)idx * 16) = make_uint4(w[0], w[1], w[2], w[3]);
        return;
    }
    if (bid < SA_QUANT + SA_XP + SA_SI) {
        int e = (bid - SA_QUANT - SA_XP) * 256 + tid;
        if (e < 16) g_hbar[e] = 0;
        if (e < BATCH * HID) {
            int b = e >> 10, j = e & 1023;
            uint8_t hb = (uint8_t)(int)hx0[e];
            int by = b >> 5, r = b & 31;
            int chunk = j >> 8, c = j & 255, sub = c >> 7, cc = c & 127;
            g_himg[(size_t)(by * 4 + chunk) * A_CHUNK_BYTES + sub * 4096 + r * 128 + (cc ^ ((r & 7) << 4))] = hb;
        }
        return;
    }
    {
        __shared__ uint32_t s_mt[3][624], s_y[3][624], s_tp[3][624];
        __shared__ int s_arr[3][256];
        __shared__ int s_state[3];
        int w = tid >> 5, lane = tid & 31;
        if (w == 0) warp_fill_perm(lane, 0u, 256, g_rngW, s_mt[0], s_y[0], s_tp[0], s_arr[0], &s_state[0]);
        else if (w == 1) warp_fill_perm(lane, 1u, 256, g_rngWI, s_mt[1], s_y[1], s_tp[1], s_arr[1], &s_state[1]);
        else if (w == 2) warp_fill_perm(lane, 2u, 16, g_rngM, s_mt[2], s_y[2], s_tp[2], s_arr[2], &s_state[2]);
    }
}

// SIMD-halfword expansion: 4 u16 -> 4 s8 in {-1,0,1}
__device__ __forceinline__ uint32_t exp4(uint32_t lo, uint32_t hi, uint32_t rp2, uint32_t ri2) {
    uint32_t t0 = __vsetgtu2(lo, rp2) + __vsetgtu2(lo, ri2);
    uint32_t t1 = __vsetgtu2(hi, rp2) + __vsetgtu2(hi, ri2);
    t0 = (t0 + 0x7FFF7FFFu) ^ 0x80008000u;
    t1 = (t1 + 0x7FFF7FFFu) ^ 0x80008000u;
    return __byte_perm(t0, t1, 0x6420);
}

// ---- launch 2: swi | W-image expand ----
#define MB_SWI    4096
#define MB_EXP    65536
__global__ __launch_bounds__(256) void setup_b_kernel() {
    const int bid = blockIdx.x;
    const int tid = threadIdx.x;

    if (bid < MB_SWI) {
        int m = bid >> 11;
        int j = bid & 2047;
        __shared__ int hist[257];
        __shared__ int sfx[258];
        for (int i = tid; i < 257; i += 256) hist[i] = 0;
        __syncthreads();
        const uint16_t* row = &g_src[m][(size_t)j * SRC_PITCH];
        for (int k = tid; k < KTOT; k += 256) atomicAdd(&hist[row[k]], 1);
        __syncthreads();
        if (tid == 0) {
            int s = 0; sfx[257] = 0;
            for (int v = 256; v >= 0; v--) { s += hist[v]; sfx[v] = s; }
        }
        __syncthreads();
        int sb = (int)row[INP];
        for (int t = tid; t < T_STEPS; t += 256) {
            int ri = g_rngWI[t], rp = g_rngW[t];
            g_C[m][t * GCOLS + j] = (float)(1025 - sfx[ri + 1] + wval(sb, rp, ri));
        }
        return;
    }
    {
        int idx = (bid - MB_SWI) * 256 + tid;
        int u     = idx & 2047;
        int chunk = (idx >> 11) & 3;
        int jx    = (idx >> 13) & 31;
        int t     = idx >> 18;
        int sub = u >> 10;
        int rem = u & 1023;
        int r = rem >> 3;
        int c16 = rem & 7;
        int m = r >> 6;
        int gcol = ((r >> 5) & 1) * HID + jx * 32 + (r & 31);
        int k = chunk * 256 + sub * 128 + ((c16 ^ (r & 7)) << 4);
        uint32_t rp2 = (uint32_t)g_rngW[t] * 0x10001u;
        uint32_t ri2 = (uint32_t)g_rngWI[t] * 0x10001u;
        const uint16_t* src = &g_src[m][(size_t)gcol * SRC_PITCH + k];
        uint4 q0 = *(const uint4*)src;
        uint4 q1 = *(const uint4*)(src + 8);
        uint4 o;
        o.x = exp4(q0.x, q0.y, rp2, ri2);
        o.y = exp4(q0.z, q0.w, rp2, ri2);
        o.z = exp4(q1.x, q1.y, rp2, ri2);
        o.w = exp4(q1.z, q1.w, rp2, ri2);
        *(uint4*)(g_w8 + (size_t)idx * 16) = o;
    }
}

__device__ __forceinline__ float clampA(float v) { return fminf(fmaxf(v, -ACC_LIM), ACC_LIM); }

__device__ __forceinline__ float fsu_mul_upd(uint32_t& m, float in0, float in1) {
    uint32_t sr = m & 0xFu;
    sr = (sr >> 1) | (((uint32_t)in1) << 3);
    int cnt = __popc(sr) * 4;
    uint32_t ip = (m >> 8) & 0xFFu;
    uint32_t ii = (m >> 16) & 0xFFu;
    float bp = (cnt > g_rngM[ip & 15u]) ? 1.0f : 0.0f;
    float bi = (cnt > g_rngM[ii & 15u]) ? 1.0f : 0.0f;
    float outv = in0 * bp + (1.0f - in0) * (1.0f - bi);
    uint32_t i0 = (uint32_t)in0;
    ip += i0; ii += 1u - i0;
    m = sr | ((ip & 0xFFu) << 8) | ((ii & 0xFFu) << 16);
    return outv;
}

__device__ __forceinline__ void mma_s8(int* d, const uint32_t* a, const uint32_t* b) {
    asm volatile(
        "mma.sync.aligned.m16n8k32.row.col.s32.s8.s8.s32 "
        "{%0,%1,%2,%3}, {%4,%5,%6,%7}, {%8,%9}, {%0,%1,%2,%3};"
        : "+r"(d[0]), "+r"(d[1]), "+r"(d[2]), "+r"(d[3])
        : "r"(a[0]), "r"(a[1]), "r"(a[2]), "r"(a[3]), "r"(b[0]), "r"(b[1]));
}

__device__ __forceinline__ void ldsm4(uint32_t* r, uint32_t addr) {
    asm volatile("ldmatrix.sync.aligned.m8n8.x4.shared.b16 {%0,%1,%2,%3}, [%4];"
        : "=r"(r[0]), "=r"(r[1]), "=r"(r[2]), "=r"(r[3]) : "r"(addr));
}

#define MBAR_INIT(addr, cnt) \
    asm volatile("mbarrier.init.shared.b64 [%0], %1;" :: "r"(addr), "r"(cnt) : "memory")
#define MBAR_ARRIVE_EXPECT(addr, tx) \
    asm volatile("mbarrier.arrive.expect_tx.shared.b64 _, [%0], %1;" :: "r"(addr), "r"(tx) : "memory")
#define BULK_G2S(dst, src, size, mbar) \
    asm volatile("cp.async.bulk.shared::cluster.global.mbarrier::complete_tx::bytes [%0], [%1], %2, [%3];" \
                 :: "r"(dst), "l"(src), "r"(size), "r"(mbar) : "memory")

__device__ __forceinline__ void mbar_wait(uint32_t addr, uint32_t parity) {
    uint32_t done;
    do {
        asm volatile(
            "{\n\t.reg .pred p;\n\t"
            "mbarrier.try_wait.parity.shared.b64 p, [%1], %2;\n\t"
            "selp.b32 %0, 1, 0, p;\n\t}"
            : "=r"(done) : "r"(addr), "r"(parity) : "memory");
    } while (!done);
}

__device__ __forceinline__ void hbar_spin(int idx, int tgt) {
    int v;
    do {
        asm volatile("ld.acquire.gpu.global.s32 %0, [%1];"
                     : "=r"(v) : "l"(&g_hbar[idx]) : "memory");
    } while (v < tgt);
}

// ---- persistent fused kernel: bulk pipeline + chunk-level h dataflow ----
// grid (32 j-blocks, 4 b-blocks) = 128 CTAs, 512 threads
__global__ __launch_bounds__(512, 1) void step_all_kernel(float* __restrict__ out,
                                                          const float* __restrict__ hx0) {
    extern __shared__ __align__(16) uint8_t pool[];

    const int tid = threadIdx.x;
    const int jx = blockIdx.x;
    const int j0 = jx * 32;
    const int b0 = blockIdx.y * 32;
    const int by = blockIdx.y;
    const int lane = tid & 31;
    const int warp = tid >> 5;
    const int mat = warp >> 3;
    const int mtile = (warp >> 2) & 1;
    const int npair = warp & 3;
    const int myhbar = by * 4 + (jx >> 3);    // chunk this CTA produces

    const uint32_t smem_base = (uint32_t)__cvta_generic_to_shared(pool);
    const uint32_t mbar0 = smem_base + MBAR_OFF;
    float* gsm = (float*)(pool + GSM_OFF);

    const int rA = mtile * 16 + ((lane >> 3) & 1) * 8 + (lane & 7);
    const uint32_t aRow = (mat ? SH_OFF : SX_OFF) + (uint32_t)(rA * 128);
    const uint32_t aXor = (uint32_t)((rA & 7) << 4);
    const uint32_t aLe  = (uint32_t)(((lane >> 4) & 1) * 16);
    const int rB = mat * 64 + npair * 16 + ((lane >> 3) & 1) * 8 + (lane & 7);
    const uint32_t bRow = SW_OFF + (uint32_t)(rB * 128);
    const uint32_t bXor = (uint32_t)((rB & 7) << 4);
    const uint32_t bLe  = (uint32_t)(((lane >> 4) & 1) * 16);

    const int8_t*  wimg = g_w8 + (size_t)jx * 4 * W_CHUNK_BYTES;
    const size_t   wtstr = (size_t)32 * 4 * W_CHUNK_BYTES;
    const uint8_t* ximg = g_ximg + (size_t)by * 4 * A_CHUNK_BYTES;
    const size_t   xtstr = (size_t)4 * 4 * A_CHUNK_BYTES;
    const uint8_t* himg = g_himg + (size_t)by * 4 * A_CHUNK_BYTES;

    int EB[2], EJ[2], EBB[2], EJL[2];
    size_t HOFF[2];
    float H[2];
#pragma unroll
    for (int i = 0; i < 2; i++) {
        int idx = tid + 512 * i;
        EBB[i] = idx >> 5; EJL[i] = idx & 31;
        EB[i] = b0 + EBB[i]; EJ[i] = j0 + EJL[i];
        int r = EBB[i], j = EJ[i];
        int chunk = j >> 8, c = j & 255, sub = c >> 7, cc = c & 127;
        HOFF[i] = (size_t)(by * 4 + chunk) * A_CHUNK_BYTES + sub * 4096 + r * 128 + (cc ^ ((r & 7) << 4));
        H[i] = hx0[(size_t)EB[i] * HID + j];     // register-resident h
    }

    float A1[2] = {0, 0}, A2[2] = {0, 0}, A3[2] = {0, 0};
    float A4[2] = {0, 0}, A5[2] = {0, 0}, A6[2] = {0, 0};
    uint32_t M1[2] = {10u, 10u}, M2[2] = {10u, 10u}, M3[2] = {10u, 10u};

    if (tid == 0) {
#pragma unroll
        for (int s = 0; s < NSTAGE; s++) MBAR_INIT(mbar0 + s * 8, 1);
    }
    __syncthreads();

    // prologue: chunks 0,1 of t=0 (W + x + h par0; hbar target 0 — trivially met)
    if (tid == 0) {
#pragma unroll
        for (int p = 0; p < 2; p++) {
            uint32_t mb = mbar0 + p * 8;
            uint32_t sb = smem_base + p * STAGE_STRIDE;
            MBAR_ARRIVE_EXPECT(mb, FILL_BYTES);
            BULK_G2S(sb + SW_OFF, wimg + (size_t)p * W_CHUNK_BYTES, W_CHUNK_BYTES, mb);
            BULK_G2S(sb + SX_OFF, ximg + (size_t)p * A_CHUNK_BYTES, A_CHUNK_BYTES, mb);
            BULK_G2S(sb + SH_OFF, himg + (size_t)p * A_CHUNK_BYTES, A_CHUNK_BYTES, mb);
        }
    }

    for (int t = 0; t < T_STEPS; t++) {
        const int8_t*  wsrc_t  = wimg + (size_t)t * wtstr;
        const int8_t*  wsrc_t1 = wsrc_t + wtstr;
        const uint8_t* xsrc_t  = ximg + (size_t)t * xtstr;
        const uint8_t* xsrc_t1 = xsrc_t + xtstr;
        const uint8_t* hsrc_t  = himg + (size_t)(t & 1) * HIMG_PAR_STRIDE;

        int d[2][4] = {{0, 0, 0, 0}, {0, 0, 0, 0}};

        for (int kt = 0; kt < 4; kt++) {
            const int g = 4 * t + kt;
            const int st = g % 3;
            mbar_wait(mbar0 + st * 8, (uint32_t)((g / 3) & 1));
            __syncthreads();
            const uint32_t sbase = smem_base + st * STAGE_STRIDE;
#pragma unroll
            for (int ks8 = 0; ks8 < 8; ks8++) {
                const uint32_t sub = (uint32_t)(ks8 >> 2);
                const uint32_t ko = (uint32_t)((ks8 & 3) * 32);
                uint32_t a[4], q[4];
                ldsm4(a, sbase + aRow + sub * 4096 + ((ko + aLe) ^ aXor));
                ldsm4(q, sbase + bRow + sub * 16384 + ((ko + bLe) ^ bXor));
                uint32_t br0[2] = {q[0], q[2]};
                uint32_t br1[2] = {q[1], q[3]};
                mma_s8(d[0], a, br0);
                mma_s8(d[1], a, br1);
            }
            if (tid == 0) {
                const int ns = (g + 2) % 3;
                uint32_t mb = mbar0 + ns * 8;
                uint32_t sb = smem_base + ns * STAGE_STRIDE;
                if (kt < 2) {
                    // chunk kt+2 of step t: W + x, then h (producers finished at t-1;
                    // spin is non-circular: targets previous-step completion only)
                    const int ck = kt + 2;
                    MBAR_ARRIVE_EXPECT(mb, FILL_BYTES);
                    BULK_G2S(sb + SW_OFF, wsrc_t + (size_t)ck * W_CHUNK_BYTES, W_CHUNK_BYTES, mb);
                    BULK_G2S(sb + SX_OFF, xsrc_t + (size_t)ck * A_CHUNK_BYTES, A_CHUNK_BYTES, mb);
                    hbar_spin(by * 4 + ck, 8 * t);
                    BULK_G2S(sb + SH_OFF, hsrc_t + (size_t)ck * A_CHUNK_BYTES, A_CHUNK_BYTES, mb);
                } else if (t + 1 < T_STEPS) {
                    // chunk kt-2 of step t+1: W + x only (h issued post-elementwise)
                    const int ck = kt - 2;
                    MBAR_ARRIVE_EXPECT(mb, FILL_BYTES);
                    BULK_G2S(sb + SW_OFF, wsrc_t1 + (size_t)ck * W_CHUNK_BYTES, W_CHUNK_BYTES, mb);
                    BULK_G2S(sb + SX_OFF, xsrc_t1 + (size_t)ck * A_CHUNK_BYTES, A_CHUNK_BYTES, mb);
                }
            }
        }

        // ---- epilogue: fragments -> gsm ----
#pragma unroll
        for (int tt = 0; tt < 2; tt++) {
            int ntile = 2 * npair + tt;
            int half = ntile >> 2;
            int cb = (ntile * 8 + (lane & 3) * 2) & 31;
            int rb = mtile * 16 + (lane >> 2);
            float* g = gsm + ((mat * 2 + half) * 32) * 32;
            g[rb * 32 + cb]           = (float)d[tt][0];
            g[rb * 32 + cb + 1]       = (float)d[tt][1];
            g[(rb + 8) * 32 + cb]     = (float)d[tt][2];
            g[(rb + 8) * 32 + cb + 1] = (float)d[tt][3];
        }
        __syncthreads();

        // ---- fused FSU elementwise (all state in registers) ----
        const size_t hpar1 = (size_t)((t + 1) & 1) * HIMG_PAR_STRIDE;
#pragma unroll
        for (int i = 0; i < 2; i++) {
            int b = EB[i], j = EJ[i], bb = EBB[i], jl = EJL[i];

            float gi_f = gsm[(0 * 32 + bb) * 32 + jl] + g_C[0][t * GCOLS + j];
            float gi_n = gsm[(1 * 32 + bb) * 32 + jl] + g_C[0][t * GCOLS + HID + j];
            float gh_f = gsm[(2 * 32 + bb) * 32 + jl] + g_C[1][t * GCOLS + j];
            float gh_n = gsm[(3 * 32 + bb) * 32 + jl] + g_C[1][t * GCOLS + HID + j];

            float h = H[i];

            A1[i] = clampA(A1[i] + (gi_f + gh_f) - 1024.5f);
            float fg_in = (A1[i] >= 1.0f) ? 1.0f : 0.0f;  A1[i] -= fg_in;

            A2[i] = clampA(A2[i] + fg_in + 1.0f);
            float fg = (A2[i] >= 2.0f) ? 1.0f : 0.0f;     A2[i] -= 2.0f * fg;

            A3[i] = clampA(A3[i] + gh_n - 512.0f);
            float hnb = (A3[i] >= 1.0f) ? 1.0f : 0.0f;    A3[i] -= hnb;

            float ng_prod = fsu_mul_upd(M1[i], fg, hnb);

            A4[i] = clampA(A4[i] + gi_n - 512.0f);
            float inb = (A4[i] >= 1.0f) ? 1.0f : 0.0f;    A4[i] -= inb;

            A5[i] = clampA(A5[i] + (inb + ng_prod) - 0.5f);
            float ng = (A5[i] >= 1.0f) ? 1.0f : 0.0f;     A5[i] -= ng;

            float fgi_prod = fsu_mul_upd(M2[i], 1.0f - fg, ng);
            float fg_prod  = fsu_mul_upd(M3[i], fg, h);

            A6[i] = clampA(A6[i] + (ng + fgi_prod + fg_prod) - 1.0f);
            float hy = (A6[i] >= 1.0f) ? 1.0f : 0.0f;     A6[i] -= hy;

            H[i] = hy;
            g_himg[hpar1 + HOFF[i]] = (uint8_t)(int)hy;
            out[((size_t)t * BATCH + b) * HID + j] = hy;
        }

        // ---- publish h, then opportunistically feed next step's chunks 0,1 ----
        if (t + 1 < T_STEPS) {
            __syncthreads();   // all himg writes of this CTA done
            if (tid == 0) {
                asm volatile("red.release.gpu.global.add.s32 [%0], 1;"
                             :: "l"(&g_hbar[myhbar]) : "memory");
                const uint8_t* hs1 = himg + hpar1;
#pragma unroll
                for (int c = 0; c < 2; c++) {
                    const int gp = 4 * (t + 1) + c;
                    uint32_t mb = mbar0 + (gp % 3) * 8;
                    uint32_t sb = smem_base + (gp % 3) * STAGE_STRIDE;
                    hbar_spin(by * 4 + c, 8 * (t + 1));
                    BULK_G2S(sb + SH_OFF, hs1 + (size_t)c * A_CHUNK_BYTES, A_CHUNK_BYTES, mb);
                }
            }
        }
    }
}

extern "C" void kernel_launch(void* const* d_in, const int* in_sizes, int n_in,
                              void* d_out, int out_size) {
    const float* x_bits = (const float*)d_in[0];
    const float* hx0    = (const float*)d_in[1];
    const float* wih    = (const float*)d_in[2];
    const float* bih    = (const float*)d_in[3];
    const float* whh    = (const float*)d_in[4];
    const float* bhh    = (const float*)d_in[5];
    float* out = (float*)d_out;

    cudaFuncSetAttribute(step_all_kernel, cudaFuncAttributeMaxDynamicSharedMemorySize, SMEM_TOTAL);

    setup_a_kernel<<<SA_QUANT + SA_XP + SA_SI + 1, 256>>>(wih, bih, whh, bhh, x_bits, hx0); // launch 1

    setup_b_kernel<<<MB_SWI + MB_EXP, 256>>>();                                             // launch 2

    dim3 grid(HID / 32, BATCH / 32);
    step_all_kernel<<<grid, 512, SMEM_TOTAL>>>(out, hx0);                                   // launch 3
}

// round 17
// speedup vs baseline: 1.1494x; 1.1494x over previous
#include <cuda_runtime.h>
#include <cstdint>

#define T_STEPS 64
#define BATCH   128
#define HID     1024
#define INP     1024
#define KTOT    1025
#define GCOLS   2048
#define SRC_PITCH 1032          // u16 pitch
#define ACC_LIM 256.0f

// smem (step kernel): FOUR 48KB stages + 16KB gsm + mbarriers = 213 KB
#define STAGE_STRIDE 49152
#define NSTAGE 4
#define SX_OFF 0
#define SH_OFF 8192
#define SW_OFF 16384
#define GSM_OFF (NSTAGE * STAGE_STRIDE)
#define MBAR_OFF (GSM_OFF + 16384)
#define SMEM_TOTAL (MBAR_OFF + 128)

#define W_CHUNK_BYTES 32768
#define A_CHUNK_BYTES 8192
#define FILL_BYTES (W_CHUNK_BYTES + 2 * A_CHUNK_BYTES)   // 49152
#define HIMG_PAR_STRIDE (4 * 4 * A_CHUNK_BYTES)

// ---- static device state ----
__device__ __align__(16) uint16_t g_src[2][GCOLS * SRC_PITCH];
__device__ float    g_C[2][T_STEPS * GCOLS];
__device__ int      g_rngW[256];
__device__ int      g_rngWI[256];
__device__ int      g_rngM[16];
// pre-swizzled stage images
__device__ __align__(16) int8_t   g_w8[(size_t)T_STEPS * 32 * 4 * W_CHUNK_BYTES];   // [t][jx][chunk][32KB]
__device__ __align__(16) uint8_t  g_ximg[(size_t)T_STEPS * 4 * 4 * A_CHUNK_BYTES];  // [t][by][chunk][8KB]
__device__ __align__(16) uint8_t  g_himg[2 * HIMG_PAR_STRIDE];                       // [par][by][chunk][8KB]
__device__ int      g_bar4[4];   // per-b-group step barrier

// ---- warp-cooperative numpy RandomState(seed).permutation(n), bit-exact ----
__device__ void warp_fill_perm(int lane, uint32_t seed, int n, int* out,
                               uint32_t* mt, uint32_t* y, uint32_t* tp,
                               int* arr, volatile int* pstate) {
    if (lane == 0) {
        uint32_t s = seed;
        for (int i = 0; i < 624; i++) { mt[i] = s; s = 1812433253u * (s ^ (s >> 30)) + (uint32_t)i + 1u; }
        *pstate = n - 1;
    }
    for (int i = lane; i < n; i += 32) arr[i] = i;
    __syncwarp();
    int i_rem = n - 1;
    while (i_rem > 0) {
        for (int k = lane; k < 623; k += 32)
            y[k] = (mt[k] & 0x80000000u) | (mt[k + 1] & 0x7fffffffu);
        __syncwarp();
        for (int k = lane; k < 227; k += 32) {
            uint32_t yy = y[k];
            mt[k] = mt[k + 397] ^ (yy >> 1) ^ ((yy & 1u) ? 0x9908b0dfu : 0u);
        }
        __syncwarp();
        for (int k = 227 + lane; k < 454; k += 32) {
            uint32_t yy = y[k];
            mt[k] = mt[k - 227] ^ (yy >> 1) ^ ((yy & 1u) ? 0x9908b0dfu : 0u);
        }
        __syncwarp();
        for (int k = 454 + lane; k < 624; k += 32) {
            uint32_t yy = (k == 623) ? ((mt[623] & 0x80000000u) | (mt[0] & 0x7fffffffu)) : y[k];
            mt[k] = mt[k - 227] ^ (yy >> 1) ^ ((yy & 1u) ? 0x9908b0dfu : 0u);
        }
        __syncwarp();
        for (int k = lane; k < 624; k += 32) {
            uint32_t v = mt[k];
            v ^= v >> 11; v ^= (v << 7) & 0x9d2c5680u; v ^= (v << 15) & 0xefc60000u; v ^= v >> 18;
            tp[k] = v;
        }
        __syncwarp();
        if (lane == 0) {
            int i = *pstate;
            int pos = 0;
            while (i > 0) {
                uint32_t mask = (uint32_t)i;
                mask |= mask >> 1; mask |= mask >> 2; mask |= mask >> 4; mask |= mask >> 8; mask |= mask >> 16;
                uint32_t j = 0; int got = 0;
                while (pos < 624) {
                    j = tp[pos++] & mask;
                    if (j <= (uint32_t)i) { got = 1; break; }
                }
                if (!got) break;
                int tmp = arr[i]; arr[i] = arr[j]; arr[j] = tmp;
                i--;
            }
            *pstate = i;
        }
        __syncwarp();
        i_rem = *pstate;
        __syncwarp();
    }
    for (int k = lane; k < n; k += 32) out[k] = arr[k];
}

__device__ __forceinline__ int wval(int s, int rp, int ri) {
    return (s > rp) + (s > ri) - 1;
}

// ---- launch 1: quant | xpack(x image) | state_init | rng ----
#define SA_QUANT 16408
#define SA_XP    2048
#define SA_SI    512
__global__ __launch_bounds__(256) void setup_a_kernel(const float* __restrict__ wih, const float* __restrict__ bih,
                                                      const float* __restrict__ whh, const float* __restrict__ bhh,
                                                      const float* __restrict__ x, const float* __restrict__ hx0) {
    const int bid = blockIdx.x;
    const int tid = threadIdx.x;

    if (bid < SA_QUANT) {
        long long idx = (long long)bid * 256 + tid;
        const long long total = 2LL * GCOLS * KTOT;
        if (idx >= total) return;
        int m = (int)(idx / (GCOLS * KTOT));
        int r = (int)(idx % (GCOLS * KTOT));
        int j = r / KTOT, k = r % KTOT;
        const float* w = m ? whh : wih;
        const float* b = m ? bhh : bih;
        float v = (k < INP) ? w[(size_t)j * INP + k] : b[j];
        v = fminf(fmaxf(v, -1.0f), 1.0f);
        v = (v + 1.0f) * 0.5f * 256.0f;
        g_src[m][(size_t)j * SRC_PITCH + k] = (uint16_t)__float2int_rn(v);
        return;
    }
    if (bid < SA_QUANT + SA_XP) {
        int idx = (bid - SA_QUANT) * 256 + tid;
        int u     = idx & 511;
        int chunk = (idx >> 9) & 3;
        int by    = (idx >> 11) & 3;
        int t     = idx >> 13;
        int sub = u >> 8;
        int rem = u & 255;
        int r = rem >> 3;
        int c16 = rem & 7;
        int b = by * 32 + r;
        int k = chunk * 256 + sub * 128 + ((c16 ^ (r & 7)) << 4);
        const float* xs = x + ((size_t)t * BATCH + b) * INP + k;
        uint32_t w[4];
#pragma unroll
        for (int q = 0; q < 4; q++) {
            float4 v = *(const float4*)(xs + q * 4);
            w[q] = (uint32_t)v.x | ((uint32_t)v.y << 8) | ((uint32_t)v.z << 16) | ((uint32_t)v.w << 24);
        }
        *(uint4*)(g_ximg + (size_t)idx * 16) = make_uint4(w[0], w[1], w[2], w[3]);
        return;
    }
    if (bid < SA_QUANT + SA_XP + SA_SI) {
        int e = (bid - SA_QUANT - SA_XP) * 256 + tid;
        if (e < 4) g_bar4[e] = 0;
        if (e < BATCH * HID) {
            int b = e >> 10, j = e & 1023;
            uint8_t hb = (uint8_t)(int)hx0[e];
            int by = b >> 5, r = b & 31;
            int chunk = j >> 8, c = j & 255, sub = c >> 7, cc = c & 127;
            g_himg[(size_t)(by * 4 + chunk) * A_CHUNK_BYTES + sub * 4096 + r * 128 + (cc ^ ((r & 7) << 4))] = hb;
        }
        return;
    }
    {
        __shared__ uint32_t s_mt[3][624], s_y[3][624], s_tp[3][624];
        __shared__ int s_arr[3][256];
        __shared__ int s_state[3];
        int w = tid >> 5, lane = tid & 31;
        if (w == 0) warp_fill_perm(lane, 0u, 256, g_rngW, s_mt[0], s_y[0], s_tp[0], s_arr[0], &s_state[0]);
        else if (w == 1) warp_fill_perm(lane, 1u, 256, g_rngWI, s_mt[1], s_y[1], s_tp[1], s_arr[1], &s_state[1]);
        else if (w == 2) warp_fill_perm(lane, 2u, 16, g_rngM, s_mt[2], s_y[2], s_tp[2], s_arr[2], &s_state[2]);
    }
}

// SIMD-halfword expansion: 4 u16 -> 4 s8 in {-1,0,1}
__device__ __forceinline__ uint32_t exp4(uint32_t lo, uint32_t hi, uint32_t rp2, uint32_t ri2) {
    uint32_t t0 = __vsetgtu2(lo, rp2) + __vsetgtu2(lo, ri2);
    uint32_t t1 = __vsetgtu2(hi, rp2) + __vsetgtu2(hi, ri2);
    t0 = (t0 + 0x7FFF7FFFu) ^ 0x80008000u;
    t1 = (t1 + 0x7FFF7FFFu) ^ 0x80008000u;
    return __byte_perm(t0, t1, 0x6420);
}

// ---- launch 2: swi | W-image expand ----
#define MB_SWI    4096
#define MB_EXP    65536
__global__ __launch_bounds__(256) void setup_b_kernel() {
    const int bid = blockIdx.x;
    const int tid = threadIdx.x;

    if (bid < MB_SWI) {
        int m = bid >> 11;
        int j = bid & 2047;
        __shared__ int hist[257];
        __shared__ int sfx[258];
        for (int i = tid; i < 257; i += 256) hist[i] = 0;
        __syncthreads();
        const uint16_t* row = &g_src[m][(size_t)j * SRC_PITCH];
        for (int k = tid; k < KTOT; k += 256) atomicAdd(&hist[row[k]], 1);
        __syncthreads();
        if (tid == 0) {
            int s = 0; sfx[257] = 0;
            for (int v = 256; v >= 0; v--) { s += hist[v]; sfx[v] = s; }
        }
        __syncthreads();
        int sb = (int)row[INP];
        for (int t = tid; t < T_STEPS; t += 256) {
            int ri = g_rngWI[t], rp = g_rngW[t];
            g_C[m][t * GCOLS + j] = (float)(1025 - sfx[ri + 1] + wval(sb, rp, ri));
        }
        return;
    }
    {
        int idx = (bid - MB_SWI) * 256 + tid;
        int u     = idx & 2047;
        int chunk = (idx >> 11) & 3;
        int jx    = (idx >> 13) & 31;
        int t     = idx >> 18;
        int sub = u >> 10;
        int rem = u & 1023;
        int r = rem >> 3;
        int c16 = rem & 7;
        int m = r >> 6;
        int gcol = ((r >> 5) & 1) * HID + jx * 32 + (r & 31);
        int k = chunk * 256 + sub * 128 + ((c16 ^ (r & 7)) << 4);
        uint32_t rp2 = (uint32_t)g_rngW[t] * 0x10001u;
        uint32_t ri2 = (uint32_t)g_rngWI[t] * 0x10001u;
        const uint16_t* src = &g_src[m][(size_t)gcol * SRC_PITCH + k];
        uint4 q0 = *(const uint4*)src;
        uint4 q1 = *(const uint4*)(src + 8);
        uint4 o;
        o.x = exp4(q0.x, q0.y, rp2, ri2);
        o.y = exp4(q0.z, q0.w, rp2, ri2);
        o.z = exp4(q1.x, q1.y, rp2, ri2);
        o.w = exp4(q1.z, q1.w, rp2, ri2);
        *(uint4*)(g_w8 + (size_t)idx * 16) = o;
    }
}

__device__ __forceinline__ float clampA(float v) { return fminf(fmaxf(v, -ACC_LIM), ACC_LIM); }

__device__ __forceinline__ float fsu_mul_upd(uint32_t& m, float in0, float in1) {
    uint32_t sr = m & 0xFu;
    sr = (sr >> 1) | (((uint32_t)in1) << 3);
    int cnt = __popc(sr) * 4;
    uint32_t ip = (m >> 8) & 0xFFu;
    uint32_t ii = (m >> 16) & 0xFFu;
    float bp = (cnt > g_rngM[ip & 15u]) ? 1.0f : 0.0f;
    float bi = (cnt > g_rngM[ii & 15u]) ? 1.0f : 0.0f;
    float outv = in0 * bp + (1.0f - in0) * (1.0f - bi);
    uint32_t i0 = (uint32_t)in0;
    ip += i0; ii += 1u - i0;
    m = sr | ((ip & 0xFFu) << 8) | ((ii & 0xFFu) << 16);
    return outv;
}

__device__ __forceinline__ void mma_s8(int* d, const uint32_t* a, const uint32_t* b) {
    asm volatile(
        "mma.sync.aligned.m16n8k32.row.col.s32.s8.s8.s32 "
        "{%0,%1,%2,%3}, {%4,%5,%6,%7}, {%8,%9}, {%0,%1,%2,%3};"
        : "+r"(d[0]), "+r"(d[1]), "+r"(d[2]), "+r"(d[3])
        : "r"(a[0]), "r"(a[1]), "r"(a[2]), "r"(a[3]), "r"(b[0]), "r"(b[1]));
}

__device__ __forceinline__ void ldsm4(uint32_t* r, uint32_t addr) {
    asm volatile("ldmatrix.sync.aligned.m8n8.x4.shared.b16 {%0,%1,%2,%3}, [%4];"
        : "=r"(r[0]), "=r"(r[1]), "=r"(r[2]), "=r"(r[3]) : "r"(addr));
}

#define MBAR_INIT(addr, cnt) \
    asm volatile("mbarrier.init.shared.b64 [%0], %1;" :: "r"(addr), "r"(cnt) : "memory")
#define MBAR_ARRIVE_EXPECT(addr, tx) \
    asm volatile("mbarrier.arrive.expect_tx.shared.b64 _, [%0], %1;" :: "r"(addr), "r"(tx) : "memory")
#define BULK_G2S(dst, src, size, mbar) \
    asm volatile("cp.async.bulk.shared::cluster.global.mbarrier::complete_tx::bytes [%0], [%1], %2, [%3];" \
                 :: "r"(dst), "l"(src), "r"(size), "r"(mbar) : "memory")

__device__ __forceinline__ void mbar_wait(uint32_t addr, uint32_t parity) {
    uint32_t done;
    do {
        asm volatile(
            "{\n\t.reg .pred p;\n\t"
            "mbarrier.try_wait.parity.shared.b64 p, [%1], %2;\n\t"
            "selp.b32 %0, 1, 0, p;\n\t}"
            : "=r"(done) : "r"(addr), "r"(parity) : "memory");
    } while (!done);
}

// ---- persistent fused kernel: 4-stage bulk pipeline, fills 3 chunks ahead ----
// grid (32 j-blocks, 4 b-blocks) = 128 CTAs, 512 threads
__global__ __launch_bounds__(512, 1) void step_all_kernel(float* __restrict__ out,
                                                          const float* __restrict__ hx0) {
    extern __shared__ __align__(16) uint8_t pool[];

    const int tid = threadIdx.x;
    const int jx = blockIdx.x;
    const int j0 = jx * 32;
    const int b0 = blockIdx.y * 32;
    const int by = blockIdx.y;
    const int lane = tid & 31;
    const int warp = tid >> 5;
    const int mat = warp >> 3;
    const int mtile = (warp >> 2) & 1;
    const int npair = warp & 3;

    const uint32_t smem_base = (uint32_t)__cvta_generic_to_shared(pool);
    const uint32_t mbar0 = smem_base + MBAR_OFF;
    float* gsm = (float*)(pool + GSM_OFF);

    const int rA = mtile * 16 + ((lane >> 3) & 1) * 8 + (lane & 7);
    const uint32_t aRow = (mat ? SH_OFF : SX_OFF) + (uint32_t)(rA * 128);
    const uint32_t aXor = (uint32_t)((rA & 7) << 4);
    const uint32_t aLe  = (uint32_t)(((lane >> 4) & 1) * 16);
    const int rB = mat * 64 + npair * 16 + ((lane >> 3) & 1) * 8 + (lane & 7);
    const uint32_t bRow = SW_OFF + (uint32_t)(rB * 128);
    const uint32_t bXor = (uint32_t)((rB & 7) << 4);
    const uint32_t bLe  = (uint32_t)(((lane >> 4) & 1) * 16);

    const int8_t*  wimg = g_w8 + (size_t)jx * 4 * W_CHUNK_BYTES;
    const size_t   wtstr = (size_t)32 * 4 * W_CHUNK_BYTES;
    const uint8_t* ximg = g_ximg + (size_t)by * 4 * A_CHUNK_BYTES;
    const size_t   xtstr = (size_t)4 * 4 * A_CHUNK_BYTES;
    const uint8_t* himg = g_himg + (size_t)by * 4 * A_CHUNK_BYTES;

    int EB[2], EJ[2], EBB[2], EJL[2];
    size_t HOFF[2];
    float H[2];
#pragma unroll
    for (int i = 0; i < 2; i++) {
        int idx = tid + 512 * i;
        EBB[i] = idx >> 5; EJL[i] = idx & 31;
        EB[i] = b0 + EBB[i]; EJ[i] = j0 + EJL[i];
        int r = EBB[i], j = EJ[i];
        int chunk = j >> 8, c = j & 255, sub = c >> 7, cc = c & 127;
        HOFF[i] = (size_t)(by * 4 + chunk) * A_CHUNK_BYTES + sub * 4096 + r * 128 + (cc ^ ((r & 7) << 4));
        H[i] = hx0[(size_t)EB[i] * HID + j];     // register-resident h
    }

    float A1[2] = {0, 0}, A2[2] = {0, 0}, A3[2] = {0, 0};
    float A4[2] = {0, 0}, A5[2] = {0, 0}, A6[2] = {0, 0};
    uint32_t M1[2] = {10u, 10u}, M2[2] = {10u, 10u}, M3[2] = {10u, 10u};

    if (tid == 0) {
#pragma unroll
        for (int s = 0; s < NSTAGE; s++) MBAR_INIT(mbar0 + s * 8, 1);
    }
    __syncthreads();

    // prologue: chunks 0,1,2 of t=0 (W + x + h par0) -> stages 0,1,2
    if (tid == 0) {
#pragma unroll
        for (int p = 0; p < 3; p++) {
            uint32_t mb = mbar0 + p * 8;
            uint32_t sb = smem_base + p * STAGE_STRIDE;
            MBAR_ARRIVE_EXPECT(mb, FILL_BYTES);
            BULK_G2S(sb + SW_OFF, wimg + (size_t)p * W_CHUNK_BYTES, W_CHUNK_BYTES, mb);
            BULK_G2S(sb + SX_OFF, ximg + (size_t)p * A_CHUNK_BYTES, A_CHUNK_BYTES, mb);
            BULK_G2S(sb + SH_OFF, himg + (size_t)p * A_CHUNK_BYTES, A_CHUNK_BYTES, mb);
        }
    }

    for (int t = 0; t < T_STEPS; t++) {
        const int8_t*  wsrc_t  = wimg + (size_t)t * wtstr;
        const int8_t*  wsrc_t1 = wsrc_t + wtstr;
        const uint8_t* xsrc_t1 = ximg + (size_t)(t + 1) * xtstr;
        const uint8_t* hsrc_t  = himg + (size_t)(t & 1) * HIMG_PAR_STRIDE;
        const uint32_t par = (uint32_t)(t & 1);

        int d[2][4] = {{0, 0, 0, 0}, {0, 0, 0, 0}};

        for (int kt = 0; kt < 4; kt++) {
            mbar_wait(mbar0 + kt * 8, par);
            __syncthreads();
            // issue fill 3 chunks ahead (stage (kt+3)&3, consumed at chunk kt-1: free)
            if (tid == 0) {
                if (kt == 0) {
                    // (t, chunk 3) full fill: W + x + h (h par t&1, barrier-protected)
                    uint32_t mb = mbar0 + 3 * 8;
                    uint32_t sb = smem_base + 3 * STAGE_STRIDE;
                    MBAR_ARRIVE_EXPECT(mb, FILL_BYTES);
                    BULK_G2S(sb + SW_OFF, wsrc_t + (size_t)3 * W_CHUNK_BYTES, W_CHUNK_BYTES, mb);
                    BULK_G2S(sb + SX_OFF, ximg + (size_t)t * xtstr + (size_t)3 * A_CHUNK_BYTES, A_CHUNK_BYTES, mb);
                    BULK_G2S(sb + SH_OFF, hsrc_t + (size_t)3 * A_CHUNK_BYTES, A_CHUNK_BYTES, mb);
                } else if (t + 1 < T_STEPS) {
                    // (t+1, chunk kt-1): W + x only; h arrives post-barrier
                    const int ck = kt - 1;
                    uint32_t mb = mbar0 + ck * 8;
                    uint32_t sb = smem_base + ck * STAGE_STRIDE;
                    MBAR_ARRIVE_EXPECT(mb, FILL_BYTES);
                    BULK_G2S(sb + SW_OFF, wsrc_t1 + (size_t)ck * W_CHUNK_BYTES, W_CHUNK_BYTES, mb);
                    BULK_G2S(sb + SX_OFF, xsrc_t1 + (size_t)ck * A_CHUNK_BYTES, A_CHUNK_BYTES, mb);
                }
            }
            const uint32_t sbase = smem_base + kt * STAGE_STRIDE;
#pragma unroll
            for (int ks8 = 0; ks8 < 8; ks8++) {
                const uint32_t sub = (uint32_t)(ks8 >> 2);
                const uint32_t ko = (uint32_t)((ks8 & 3) * 32);
                uint32_t a[4], q[4];
                ldsm4(a, sbase + aRow + sub * 4096 + ((ko + aLe) ^ aXor));
                ldsm4(q, sbase + bRow + sub * 16384 + ((ko + bLe) ^ bXor));
                uint32_t br0[2] = {q[0], q[2]};
                uint32_t br1[2] = {q[1], q[3]};
                mma_s8(d[0], a, br0);
                mma_s8(d[1], a, br1);
            }
        }

        // ---- epilogue: fragments -> gsm ----
#pragma unroll
        for (int tt = 0; tt < 2; tt++) {
            int ntile = 2 * npair + tt;
            int half = ntile >> 2;
            int cb = (ntile * 8 + (lane & 3) * 2) & 31;
            int rb = mtile * 16 + (lane >> 2);
            float* g = gsm + ((mat * 2 + half) * 32) * 32;
            g[rb * 32 + cb]           = (float)d[tt][0];
            g[rb * 32 + cb + 1]       = (float)d[tt][1];
            g[(rb + 8) * 32 + cb]     = (float)d[tt][2];
            g[(rb + 8) * 32 + cb + 1] = (float)d[tt][3];
        }
        __syncthreads();

        // ---- fused FSU elementwise (register state) ----
        const size_t hpar1 = (size_t)((t + 1) & 1) * HIMG_PAR_STRIDE;
#pragma unroll
        for (int i = 0; i < 2; i++) {
            int b = EB[i], j = EJ[i], bb = EBB[i], jl = EJL[i];

            float gi_f = gsm[(0 * 32 + bb) * 32 + jl] + g_C[0][t * GCOLS + j];
            float gi_n = gsm[(1 * 32 + bb) * 32 + jl] + g_C[0][t * GCOLS + HID + j];
            float gh_f = gsm[(2 * 32 + bb) * 32 + jl] + g_C[1][t * GCOLS + j];
            float gh_n = gsm[(3 * 32 + bb) * 32 + jl] + g_C[1][t * GCOLS + HID + j];

            float h = H[i];

            A1[i] = clampA(A1[i] + (gi_f + gh_f) - 1024.5f);
            float fg_in = (A1[i] >= 1.0f) ? 1.0f : 0.0f;  A1[i] -= fg_in;

            A2[i] = clampA(A2[i] + fg_in + 1.0f);
            float fg = (A2[i] >= 2.0f) ? 1.0f : 0.0f;     A2[i] -= 2.0f * fg;

            A3[i] = clampA(A3[i] + gh_n - 512.0f);
            float hnb = (A3[i] >= 1.0f) ? 1.0f : 0.0f;    A3[i] -= hnb;

            float ng_prod = fsu_mul_upd(M1[i], fg, hnb);

            A4[i] = clampA(A4[i] + gi_n - 512.0f);
            float inb = (A4[i] >= 1.0f) ? 1.0f : 0.0f;    A4[i] -= inb;

            A5[i] = clampA(A5[i] + (inb + ng_prod) - 0.5f);
            float ng = (A5[i] >= 1.0f) ? 1.0f : 0.0f;     A5[i] -= ng;

            float fgi_prod = fsu_mul_upd(M2[i], 1.0f - fg, ng);
            float fg_prod  = fsu_mul_upd(M3[i], fg, h);

            A6[i] = clampA(A6[i] + (ng + fgi_prod + fg_prod) - 1.0f);
            float hy = (A6[i] >= 1.0f) ? 1.0f : 0.0f;     A6[i] -= hy;

            H[i] = hy;
            g_himg[hpar1 + HOFF[i]] = (uint8_t)(int)hy;
            out[((size_t)t * BATCH + b) * HID + j] = hy;
        }

        // ---- per-b-group barrier + post-barrier h bulks for t+1 chunks 0,1,2 ----
        if (t + 1 < T_STEPS) {
            __syncthreads();
            if (tid == 0) {
                asm volatile("red.release.gpu.global.add.s32 [%0], 1;"
                             :: "l"(&g_bar4[by]) : "memory");
                const int tgt = 32 * (t + 1);
                int v;
                do {
                    asm volatile("ld.acquire.gpu.global.s32 %0, [%1];"
                                 : "=r"(v) : "l"(&g_bar4[by]) : "memory");
                } while (v < tgt);
                const uint8_t* hs1 = himg + hpar1;
#pragma unroll
                for (int c = 0; c < 3; c++) {
                    uint32_t mb = mbar0 + c * 8;
                    uint32_t sb = smem_base + c * STAGE_STRIDE;
                    BULK_G2S(sb + SH_OFF, hs1 + (size_t)c * A_CHUNK_BYTES, A_CHUNK_BYTES, mb);
                }
            }
        }
    }
}

extern "C" void kernel_launch(void* const* d_in, const int* in_sizes, int n_in,
                              void* d_out, int out_size) {
    const float* x_bits = (const float*)d_in[0];
    const float* hx0    = (const float*)d_in[1];
    const float* wih    = (const float*)d_in[2];
    const float* bih    = (const float*)d_in[3];
    const float* whh    = (const float*)d_in[4];
    const float* bhh    = (const float*)d_in[5];
    float* out = (float*)d_out;

    cudaFuncSetAttribute(step_all_kernel, cudaFuncAttributeMaxDynamicSharedMemorySize, SMEM_TOTAL);

    setup_a_kernel<<<SA_QUANT + SA_XP + SA_SI + 1, 256>>>(wih, bih, whh, bhh, x_bits, hx0); // launch 1

    setup_b_kernel<<<MB_SWI + MB_EXP, 256>>>();                                             // launch 2

    dim3 grid(HID / 32, BATCH / 32);
    step_all_kernel<<<grid, 512, SMEM_TOTAL>>>(out, hx0);                                   // launch 3
}